// round 4
// baseline (speedup 1.0000x reference)
#include <cuda_runtime.h>
#include <cuda_bf16.h>

#define N_NODES  100000
#define N_EDGES  1600000
#define N_GRAPHS 1000
#define SCAN_B   1024
#define N_SBLK   ((N_NODES + SCAN_B - 1) / SCAN_B)   // 98

// ---------------- scratch (static __device__, no allocs) ----------------
__device__ float g_deg[N_NODES];
__device__ float g_dinv[N_NODES];
__device__ int   g_cnt[N_NODES];
__device__ int   g_cur[N_NODES];
__device__ int   g_rs[N_NODES + 1];
__device__ int   g_bsum[N_SBLK];
__device__ int   g_csr_src[N_EDGES];
__device__ float g_csr_w[N_EDGES];
__device__ float g_m[N_NODES * 64];
__device__ float g_h[N_NODES * 64];
__device__ float g_m2[N_NODES * 32];
__device__ float g_h2[N_NODES * 32];
__device__ float g_pool[N_GRAPHS * 32];

// ---------------- degree + in-degree count ----------------
__global__ void edge_prep_kernel(const int* __restrict__ dst, const float* __restrict__ w, int E) {
    int e = blockIdx.x * blockDim.x + threadIdx.x;
    if (e < E) {
        int d = dst[e];
        atomicAdd(&g_deg[d], w[e]);
        atomicAdd(&g_cnt[d], 1);
    }
}

__global__ void dinv_kernel(int n) {
    int i = blockIdx.x * blockDim.x + threadIdx.x;
    if (i < n) {
        float d = g_deg[i] + 1.0f;  // self loop weight 1
        g_dinv[i] = rsqrtf(fmaxf(d, 1e-12f));
    }
}

// ---------------- 3-kernel exclusive scan: g_rs[i+1] = incl_scan(g_cnt)[i] ----------------
__global__ void scan1_kernel(int n) {
    __shared__ int wsum[32];
    int i = blockIdx.x * SCAN_B + threadIdx.x;
    int lane = threadIdx.x & 31, wid = threadIdx.x >> 5;
    int v = (i < n) ? g_cnt[i] : 0;
    int s = v;
#pragma unroll
    for (int o = 1; o < 32; o <<= 1) {
        int t = __shfl_up_sync(0xffffffffu, s, o);
        if (lane >= o) s += t;
    }
    if (lane == 31) wsum[wid] = s;
    __syncthreads();
    if (wid == 0) {
        int ws = wsum[lane];
#pragma unroll
        for (int o = 1; o < 32; o <<= 1) {
            int t = __shfl_up_sync(0xffffffffu, ws, o);
            if (lane >= o) ws += t;
        }
        wsum[lane] = ws;
    }
    __syncthreads();
    int off = (wid > 0) ? wsum[wid - 1] : 0;
    int incl = s + off;
    if (i < n) g_rs[i + 1] = incl;
    if (threadIdx.x == SCAN_B - 1) g_bsum[blockIdx.x] = incl;
}

__global__ void scan2_kernel(int nb) {   // nb <= 128, 128 threads
    __shared__ int sm[4];
    int lane = threadIdx.x & 31, wid = threadIdx.x >> 5;
    int v = (threadIdx.x < nb) ? g_bsum[threadIdx.x] : 0;
    int s = v;
#pragma unroll
    for (int o = 1; o < 32; o <<= 1) {
        int t = __shfl_up_sync(0xffffffffu, s, o);
        if (lane >= o) s += t;
    }
    if (lane == 31) sm[wid] = s;
    __syncthreads();
    int off = 0;
    for (int w = 0; w < wid; w++) off += sm[w];
    if (threadIdx.x < nb) g_bsum[threadIdx.x] = s + off;
}

__global__ void scan3_kernel(int n) {
    if (blockIdx.x == 0) return;
    int i = blockIdx.x * SCAN_B + threadIdx.x;
    if (i < n) g_rs[i + 1] += g_bsum[blockIdx.x - 1];
}

// ---------------- scatter into CSR (by dst), with fused norm weight ----------------
__global__ void scatter_kernel(const int* __restrict__ src, const int* __restrict__ dst,
                               const float* __restrict__ w, int E) {
    int e = blockIdx.x * blockDim.x + threadIdx.x;
    if (e >= E) return;
    int s = src[e], d = dst[e];
    int pos = g_rs[d] + atomicAdd(&g_cur[d], 1);
    g_csr_src[pos] = s;
    g_csr_w[pos] = g_dinv[s] * w[e] * g_dinv[d];
}

// ---------------- register-blocked GEMM: out[N,M] = X[N,K] @ W[K,M] ----------------
// 4 rows x 8 cols per thread; Ws staged in KP-sized K phases to fit 48KB smem.
template <int K, int M, int TR, int KP>
__global__ void __launch_bounds__(TR * M / 32)
gemm_kernel(const float* __restrict__ X, const float* __restrict__ W,
            float* __restrict__ out, int nrows) {
    __shared__ float Ws[KP * M];
    __shared__ float Xs[TR * K];
    constexpr int T = TR * M / 32;

    int row0 = blockIdx.x * TR;
    int nr = nrows - row0; if (nr > TR) nr = TR;
    const float4* Xg = reinterpret_cast<const float4*>(X + (size_t)row0 * K);
    for (int i = threadIdx.x; i < nr * K / 4; i += T)
        reinterpret_cast<float4*>(Xs)[i] = Xg[i];

    int tx = threadIdx.x % (M / 8);
    int ty = threadIdx.x / (M / 8);
    int c0 = tx * 8;
    int r0 = ty * 4;

    float acc[4][8];
#pragma unroll
    for (int r = 0; r < 4; r++)
#pragma unroll
        for (int c = 0; c < 8; c++) acc[r][c] = 0.f;

    for (int ph = 0; ph < K; ph += KP) {
        for (int i = threadIdx.x; i < KP * M / 4; i += T)
            reinterpret_cast<float4*>(Ws)[i] = reinterpret_cast<const float4*>(W + ph * M)[i];
        __syncthreads();

#pragma unroll 2
        for (int kc = 0; kc < KP; kc += 4) {
            float4 xa[4];
#pragma unroll
            for (int r = 0; r < 4; r++)
                xa[r] = *reinterpret_cast<const float4*>(&Xs[(r0 + r) * K + ph + kc]);
#pragma unroll
            for (int kk = 0; kk < 4; kk++) {
                float4 wa = *reinterpret_cast<const float4*>(&Ws[(kc + kk) * M + c0]);
                float4 wb = *reinterpret_cast<const float4*>(&Ws[(kc + kk) * M + c0 + 4]);
#pragma unroll
                for (int r = 0; r < 4; r++) {
                    float xv = (&xa[r].x)[kk];
                    acc[r][0] += xv * wa.x; acc[r][1] += xv * wa.y;
                    acc[r][2] += xv * wa.z; acc[r][3] += xv * wa.w;
                    acc[r][4] += xv * wb.x; acc[r][5] += xv * wb.y;
                    acc[r][6] += xv * wb.z; acc[r][7] += xv * wb.w;
                }
            }
        }
        __syncthreads();
    }

#pragma unroll
    for (int r = 0; r < 4; r++) {
        int row = row0 + r0 + r;
        if (row < nrows) {
            *reinterpret_cast<float4*>(&out[(size_t)row * M + c0]) =
                make_float4(acc[r][0], acc[r][1], acc[r][2], acc[r][3]);
            *reinterpret_cast<float4*>(&out[(size_t)row * M + c0 + 4]) =
                make_float4(acc[r][4], acc[r][5], acc[r][6], acc[r][7]);
        }
    }
}

// ---------------- CSR node aggregation, fused self-loop + bias + relu ----------------
// FD4 threads per node (float4 features each): 16 for F=64, 8 for F=32.
template <int FD4>
__global__ void node_agg_kernel(const float* __restrict__ m, const float* __restrict__ b,
                                float* __restrict__ h, int n) {
    int gid = (blockIdx.x * blockDim.x + threadIdx.x) / FD4;
    int f = threadIdx.x % FD4;
    if (gid >= n) return;
    const float4* m4 = reinterpret_cast<const float4*>(m);

    float di = g_dinv[gid];
    float ws = di * di;                        // self-loop weight
    float4 acc = m4[(size_t)gid * FD4 + f];
    acc.x *= ws; acc.y *= ws; acc.z *= ws; acc.w *= ws;

    int p = g_rs[gid], p1 = g_rs[gid + 1];
    for (; p + 1 < p1; p += 2) {
        int   s0 = g_csr_src[p],     s1 = g_csr_src[p + 1];
        float w0 = g_csr_w[p],       w1 = g_csr_w[p + 1];
        float4 v0 = m4[(size_t)s0 * FD4 + f];
        float4 v1 = m4[(size_t)s1 * FD4 + f];
        acc.x += v0.x * w0 + v1.x * w1;
        acc.y += v0.y * w0 + v1.y * w1;
        acc.z += v0.z * w0 + v1.z * w1;
        acc.w += v0.w * w0 + v1.w * w1;
    }
    if (p < p1) {
        int s0 = g_csr_src[p]; float w0 = g_csr_w[p];
        float4 v0 = m4[(size_t)s0 * FD4 + f];
        acc.x += v0.x * w0; acc.y += v0.y * w0;
        acc.z += v0.z * w0; acc.w += v0.w * w0;
    }

    float4 bb = reinterpret_cast<const float4*>(b)[f];
    acc.x = fmaxf(acc.x + bb.x, 0.f);
    acc.y = fmaxf(acc.y + bb.y, 0.f);
    acc.z = fmaxf(acc.z + bb.z, 0.f);
    acc.w = fmaxf(acc.w + bb.w, 0.f);
    reinterpret_cast<float4*>(h)[(size_t)gid * FD4 + f] = acc;
}

// ---------------- pooling: g[graph] += h2[node], sorted run-length flush ----------------
__global__ void pool_kernel(const float* __restrict__ h2, const int* __restrict__ ngi, int n) {
    int lane = threadIdx.x;              // 32 threads = 32 features
    int start = blockIdx.x * 128;
    if (start >= n) return;
    int end = start + 128; if (end > n) end = n;
    float acc = 0.f;
    int cur = ngi[start];
    for (int i = start; i < end; i++) {
        int gi = ngi[i];
        if (gi != cur) {
            atomicAdd(&g_pool[cur * 32 + lane], acc);
            acc = 0.f; cur = gi;
        }
        acc += h2[i * 32 + lane];
    }
    atomicAdd(&g_pool[cur * 32 + lane], acc);
}

// ---------------- MLP head: relu(g@Wm1+bm1) @ Wm2 + bm2 ----------------
__global__ void mlp_kernel(const float* __restrict__ Wm1, const float* __restrict__ bm1,
                           const float* __restrict__ Wm2, const float* __restrict__ bm2,
                           float* __restrict__ out) {
    __shared__ float gs[32];
    __shared__ float g2s[128];
    int b = blockIdx.x, t = threadIdx.x;
    if (t < 32) gs[t] = g_pool[b * 32 + t];
    __syncthreads();
    float acc = bm1[t];
#pragma unroll
    for (int k = 0; k < 32; k++) acc += gs[k] * Wm1[k * 128 + t];
    g2s[t] = fmaxf(acc, 0.f);
    __syncthreads();
    if (t < 2) {
        float a = bm2[t];
#pragma unroll
        for (int k = 0; k < 128; k++) a += g2s[k] * Wm2[k * 2 + t];
        out[b * 2 + t] = a;
    }
}

// ---------------- host ----------------
extern "C" void kernel_launch(void* const* d_in, const int* in_sizes, int n_in,
                              void* d_out, int out_size) {
    const float* x   = (const float*)d_in[0];
    const int*   ei  = (const int*)d_in[1];
    const float* ew  = (const float*)d_in[2];
    const int*   ngi = (const int*)d_in[3];
    const float* W0  = (const float*)d_in[4];
    const float* b0  = (const float*)d_in[5];
    const float* W1  = (const float*)d_in[6];
    const float* b1  = (const float*)d_in[7];
    const float* Wm1 = (const float*)d_in[8];
    const float* bm1 = (const float*)d_in[9];
    const float* Wm2 = (const float*)d_in[10];
    const float* bm2 = (const float*)d_in[11];
    float* out = (float*)d_out;

    const int* srcp = ei;
    const int* dstp = ei + N_EDGES;

    void *p_deg, *p_cnt, *p_cur, *p_rs, *p_g, *p_m, *p_h, *p_m2, *p_h2;
    cudaGetSymbolAddress(&p_deg, g_deg);
    cudaGetSymbolAddress(&p_cnt, g_cnt);
    cudaGetSymbolAddress(&p_cur, g_cur);
    cudaGetSymbolAddress(&p_rs,  g_rs);
    cudaGetSymbolAddress(&p_g,   g_pool);
    cudaGetSymbolAddress(&p_m,   g_m);
    cudaGetSymbolAddress(&p_h,   g_h);
    cudaGetSymbolAddress(&p_m2,  g_m2);
    cudaGetSymbolAddress(&p_h2,  g_h2);

    cudaMemsetAsync(p_deg, 0, N_NODES * sizeof(float));
    cudaMemsetAsync(p_cnt, 0, N_NODES * sizeof(int));
    cudaMemsetAsync(p_cur, 0, N_NODES * sizeof(int));
    cudaMemsetAsync(p_rs,  0, sizeof(int));
    cudaMemsetAsync(p_g,   0, N_GRAPHS * 32 * sizeof(float));

    // normalization + CSR build (reused by both layers)
    edge_prep_kernel<<<(N_EDGES + 255) / 256, 256>>>(dstp, ew, N_EDGES);
    dinv_kernel<<<(N_NODES + 255) / 256, 256>>>(N_NODES);
    scan1_kernel<<<N_SBLK, SCAN_B>>>(N_NODES);
    scan2_kernel<<<1, 128>>>(N_SBLK);
    scan3_kernel<<<N_SBLK, SCAN_B>>>(N_NODES);
    scatter_kernel<<<(N_EDGES + 255) / 256, 256>>>(srcp, dstp, ew, N_EDGES);

    // layer 0: 128 -> 64  (GEMM then fused CSR aggregation)
    gemm_kernel<128, 64, 64, 64><<<(N_NODES + 63) / 64, 128>>>(x, W0, (float*)p_m, N_NODES);
    node_agg_kernel<16><<<(N_NODES * 16 + 255) / 256, 256>>>((const float*)p_m, b0, (float*)p_h, N_NODES);

    // layer 1: 64 -> 32
    gemm_kernel<64, 32, 128, 64><<<(N_NODES + 127) / 128, 128>>>((const float*)p_h, W1, (float*)p_m2, N_NODES);
    node_agg_kernel<8><<<(N_NODES * 8 + 255) / 256, 256>>>((const float*)p_m2, b1, (float*)p_h2, N_NODES);

    // pooling + MLP
    pool_kernel<<<(N_NODES + 127) / 128, 32>>>((const float*)p_h2, ngi, N_NODES);
    mlp_kernel<<<N_GRAPHS, 128>>>(Wm1, bm1, Wm2, bm2, out);
}

// round 5
// speedup vs baseline: 1.5759x; 1.5759x over previous
#include <cuda_runtime.h>
#include <cuda_bf16.h>

#define N_NODES  100000
#define N_EDGES  1600000
#define N_GRAPHS 1000
#define SCAN_B   1024
#define N_SBLK   ((N_NODES + SCAN_B - 1) / SCAN_B)   // 98

// ---------------- scratch (static __device__, no allocs) ----------------
__device__ float g_deg[N_NODES];
__device__ float g_dinv[N_NODES];
__device__ int   g_cnt[N_NODES];
__device__ int   g_rank[N_EDGES];
__device__ int   g_rs[N_NODES + 1];
__device__ int   g_bsum[N_SBLK];
__device__ int2  g_csr[N_EDGES];          // {src, weight-as-bits}
__device__ float g_m[N_NODES * 64];
__device__ float g_h[N_NODES * 64];
__device__ float g_m2[N_NODES * 32];
__device__ float g_h2[N_NODES * 32];
__device__ float g_pool[N_GRAPHS * 32];

// ---------------- degree + in-degree count + rank capture ----------------
__global__ void edge_prep_kernel(const int* __restrict__ dst, const float* __restrict__ w, int E) {
    int e = blockIdx.x * blockDim.x + threadIdx.x;
    if (e < E) {
        int d = dst[e];
        atomicAdd(&g_deg[d], w[e]);
        g_rank[e] = atomicAdd(&g_cnt[d], 1);   // coalesced rank store
    }
}

__global__ void dinv_kernel(int n) {
    int i = blockIdx.x * blockDim.x + threadIdx.x;
    if (i < n) {
        float d = g_deg[i] + 1.0f;  // self loop weight 1
        g_dinv[i] = rsqrtf(fmaxf(d, 1e-12f));
    }
}

// ---------------- 3-kernel scan: g_rs[i+1] = incl_scan(g_cnt)[i], g_rs[0]=0 ----------------
__global__ void scan1_kernel(int n) {
    __shared__ int wsum[32];
    int i = blockIdx.x * SCAN_B + threadIdx.x;
    int lane = threadIdx.x & 31, wid = threadIdx.x >> 5;
    int v = (i < n) ? g_cnt[i] : 0;
    int s = v;
#pragma unroll
    for (int o = 1; o < 32; o <<= 1) {
        int t = __shfl_up_sync(0xffffffffu, s, o);
        if (lane >= o) s += t;
    }
    if (lane == 31) wsum[wid] = s;
    __syncthreads();
    if (wid == 0) {
        int ws = wsum[lane];
#pragma unroll
        for (int o = 1; o < 32; o <<= 1) {
            int t = __shfl_up_sync(0xffffffffu, ws, o);
            if (lane >= o) ws += t;
        }
        wsum[lane] = ws;
    }
    __syncthreads();
    int off = (wid > 0) ? wsum[wid - 1] : 0;
    int incl = s + off;
    if (i < n) g_rs[i + 1] = incl;
    if (threadIdx.x == SCAN_B - 1) g_bsum[blockIdx.x] = incl;
}

__global__ void scan2_kernel(int nb) {   // nb <= 128, 128 threads
    __shared__ int sm[4];
    int lane = threadIdx.x & 31, wid = threadIdx.x >> 5;
    int v = (threadIdx.x < nb) ? g_bsum[threadIdx.x] : 0;
    int s = v;
#pragma unroll
    for (int o = 1; o < 32; o <<= 1) {
        int t = __shfl_up_sync(0xffffffffu, s, o);
        if (lane >= o) s += t;
    }
    if (lane == 31) sm[wid] = s;
    __syncthreads();
    int off = 0;
    for (int w = 0; w < wid; w++) off += sm[w];
    if (threadIdx.x < nb) g_bsum[threadIdx.x] = s + off;
}

__global__ void scan3_kernel(int n) {
    if (blockIdx.x == 0) return;
    int i = blockIdx.x * SCAN_B + threadIdx.x;
    if (i < n) g_rs[i + 1] += g_bsum[blockIdx.x - 1];
}

// ---------------- scatter into CSR (atomic-free, single packed STG.64) ----------------
__global__ void scatter_kernel(const int* __restrict__ src, const int* __restrict__ dst,
                               const float* __restrict__ w, int E) {
    int e = blockIdx.x * blockDim.x + threadIdx.x;
    if (e >= E) return;
    int s = src[e], d = dst[e];
    int pos = g_rs[d] + g_rank[e];
    float nw = g_dinv[s] * w[e] * g_dinv[d];
    g_csr[pos] = make_int2(s, __float_as_int(nw));
}

// ---------------- register-blocked GEMM: out[N,M] = X[N,K] @ W[K,M] ----------------
// 4 rows x 8 cols per thread; both X and W staged in KP-sized K phases.
template <int K, int M, int TR, int KP>
__global__ void __launch_bounds__(TR * M / 32)
gemm_kernel(const float* __restrict__ X, const float* __restrict__ W,
            float* __restrict__ out, int nrows) {
    __shared__ float Ws[KP * M];
    __shared__ float Xs[TR * KP];
    constexpr int T = TR * M / 32;

    int row0 = blockIdx.x * TR;
    int nr = nrows - row0; if (nr > TR) nr = TR;
    const float4* Xg = reinterpret_cast<const float4*>(X);

    int tx = threadIdx.x % (M / 8);
    int ty = threadIdx.x / (M / 8);
    int c0 = tx * 8;
    int r0 = ty * 4;

    float acc[4][8];
#pragma unroll
    for (int r = 0; r < 4; r++)
#pragma unroll
        for (int c = 0; c < 8; c++) acc[r][c] = 0.f;

    for (int ph = 0; ph < K; ph += KP) {
        for (int i = threadIdx.x; i < KP * M / 4; i += T)
            reinterpret_cast<float4*>(Ws)[i] = reinterpret_cast<const float4*>(W + ph * M)[i];
        for (int i = threadIdx.x; i < nr * (KP / 4); i += T) {
            int row = i / (KP / 4), col = i % (KP / 4);
            reinterpret_cast<float4*>(Xs)[row * (KP / 4) + col] =
                Xg[((size_t)(row0 + row) * K + ph) / 4 + col];
        }
        __syncthreads();

#pragma unroll 2
        for (int kc = 0; kc < KP; kc += 4) {
            float4 xa[4];
#pragma unroll
            for (int r = 0; r < 4; r++)
                xa[r] = *reinterpret_cast<const float4*>(&Xs[(r0 + r) * KP + kc]);
#pragma unroll
            for (int kk = 0; kk < 4; kk++) {
                float4 wa = *reinterpret_cast<const float4*>(&Ws[(kc + kk) * M + c0]);
                float4 wb = *reinterpret_cast<const float4*>(&Ws[(kc + kk) * M + c0 + 4]);
#pragma unroll
                for (int r = 0; r < 4; r++) {
                    float xv = (&xa[r].x)[kk];
                    acc[r][0] += xv * wa.x; acc[r][1] += xv * wa.y;
                    acc[r][2] += xv * wa.z; acc[r][3] += xv * wa.w;
                    acc[r][4] += xv * wb.x; acc[r][5] += xv * wb.y;
                    acc[r][6] += xv * wb.z; acc[r][7] += xv * wb.w;
                }
            }
        }
        __syncthreads();
    }

#pragma unroll
    for (int r = 0; r < 4; r++) {
        int row = row0 + r0 + r;
        if (row < nrows) {
            *reinterpret_cast<float4*>(&out[(size_t)row * M + c0]) =
                make_float4(acc[r][0], acc[r][1], acc[r][2], acc[r][3]);
            *reinterpret_cast<float4*>(&out[(size_t)row * M + c0 + 4]) =
                make_float4(acc[r][4], acc[r][5], acc[r][6], acc[r][7]);
        }
    }
}

// ---------------- CSR node aggregation, fused self-loop + bias + relu ----------------
// FD4 threads per node (float4 features each): 16 for F=64, 8 for F=32.
template <int FD4>
__global__ void node_agg_kernel(const float* __restrict__ m, const float* __restrict__ b,
                                float* __restrict__ h, int n) {
    int gid = (blockIdx.x * blockDim.x + threadIdx.x) / FD4;
    int f = threadIdx.x % FD4;
    if (gid >= n) return;
    const float4* m4 = reinterpret_cast<const float4*>(m);

    float di = g_dinv[gid];
    float ws = di * di;                        // self-loop weight
    float4 acc = m4[(size_t)gid * FD4 + f];
    acc.x *= ws; acc.y *= ws; acc.z *= ws; acc.w *= ws;

    int p = g_rs[gid], p1 = g_rs[gid + 1];
    for (; p + 1 < p1; p += 2) {
        int2  c0 = g_csr[p], c1 = g_csr[p + 1];
        float w0 = __int_as_float(c0.y), w1 = __int_as_float(c1.y);
        float4 v0 = m4[(size_t)c0.x * FD4 + f];
        float4 v1 = m4[(size_t)c1.x * FD4 + f];
        acc.x += v0.x * w0 + v1.x * w1;
        acc.y += v0.y * w0 + v1.y * w1;
        acc.z += v0.z * w0 + v1.z * w1;
        acc.w += v0.w * w0 + v1.w * w1;
    }
    if (p < p1) {
        int2 c0 = g_csr[p];
        float w0 = __int_as_float(c0.y);
        float4 v0 = m4[(size_t)c0.x * FD4 + f];
        acc.x += v0.x * w0; acc.y += v0.y * w0;
        acc.z += v0.z * w0; acc.w += v0.w * w0;
    }

    float4 bb = reinterpret_cast<const float4*>(b)[f];
    acc.x = fmaxf(acc.x + bb.x, 0.f);
    acc.y = fmaxf(acc.y + bb.y, 0.f);
    acc.z = fmaxf(acc.z + bb.z, 0.f);
    acc.w = fmaxf(acc.w + bb.w, 0.f);
    reinterpret_cast<float4*>(h)[(size_t)gid * FD4 + f] = acc;
}

// ---------------- pooling: g[graph] += h2[node], sorted run-length flush ----------------
__global__ void pool_kernel(const float* __restrict__ h2, const int* __restrict__ ngi, int n) {
    int lane = threadIdx.x;              // 32 threads = 32 features
    int start = blockIdx.x * 128;
    if (start >= n) return;
    int end = start + 128; if (end > n) end = n;
    float acc = 0.f;
    int cur = ngi[start];
    for (int i = start; i < end; i++) {
        int gi = ngi[i];
        if (gi != cur) {
            atomicAdd(&g_pool[cur * 32 + lane], acc);
            acc = 0.f; cur = gi;
        }
        acc += h2[i * 32 + lane];
    }
    atomicAdd(&g_pool[cur * 32 + lane], acc);
}

// ---------------- MLP head: relu(g@Wm1+bm1) @ Wm2 + bm2 ----------------
__global__ void mlp_kernel(const float* __restrict__ Wm1, const float* __restrict__ bm1,
                           const float* __restrict__ Wm2, const float* __restrict__ bm2,
                           float* __restrict__ out) {
    __shared__ float gs[32];
    __shared__ float g2s[128];
    int b = blockIdx.x, t = threadIdx.x;
    if (t < 32) gs[t] = g_pool[b * 32 + t];
    __syncthreads();
    float acc = bm1[t];
#pragma unroll
    for (int k = 0; k < 32; k++) acc += gs[k] * Wm1[k * 128 + t];
    g2s[t] = fmaxf(acc, 0.f);
    __syncthreads();
    if (t < 2) {
        float a = bm2[t];
#pragma unroll
        for (int k = 0; k < 128; k++) a += g2s[k] * Wm2[k * 2 + t];
        out[b * 2 + t] = a;
    }
}

// ---------------- host ----------------
extern "C" void kernel_launch(void* const* d_in, const int* in_sizes, int n_in,
                              void* d_out, int out_size) {
    const float* x   = (const float*)d_in[0];
    const int*   ei  = (const int*)d_in[1];
    const float* ew  = (const float*)d_in[2];
    const int*   ngi = (const int*)d_in[3];
    const float* W0  = (const float*)d_in[4];
    const float* b0  = (const float*)d_in[5];
    const float* W1  = (const float*)d_in[6];
    const float* b1  = (const float*)d_in[7];
    const float* Wm1 = (const float*)d_in[8];
    const float* bm1 = (const float*)d_in[9];
    const float* Wm2 = (const float*)d_in[10];
    const float* bm2 = (const float*)d_in[11];
    float* out = (float*)d_out;

    const int* srcp = ei;
    const int* dstp = ei + N_EDGES;

    void *p_deg, *p_cnt, *p_rs, *p_g, *p_m, *p_h, *p_m2, *p_h2;
    cudaGetSymbolAddress(&p_deg, g_deg);
    cudaGetSymbolAddress(&p_cnt, g_cnt);
    cudaGetSymbolAddress(&p_rs,  g_rs);
    cudaGetSymbolAddress(&p_g,   g_pool);
    cudaGetSymbolAddress(&p_m,   g_m);
    cudaGetSymbolAddress(&p_h,   g_h);
    cudaGetSymbolAddress(&p_m2,  g_m2);
    cudaGetSymbolAddress(&p_h2,  g_h2);

    cudaMemsetAsync(p_deg, 0, N_NODES * sizeof(float));
    cudaMemsetAsync(p_cnt, 0, N_NODES * sizeof(int));
    cudaMemsetAsync(p_rs,  0, sizeof(int));
    cudaMemsetAsync(p_g,   0, N_GRAPHS * 32 * sizeof(float));

    // normalization + CSR build (reused by both layers)
    edge_prep_kernel<<<(N_EDGES + 255) / 256, 256>>>(dstp, ew, N_EDGES);
    dinv_kernel<<<(N_NODES + 255) / 256, 256>>>(N_NODES);
    scan1_kernel<<<N_SBLK, SCAN_B>>>(N_NODES);
    scan2_kernel<<<1, 128>>>(N_SBLK);
    scan3_kernel<<<N_SBLK, SCAN_B>>>(N_NODES);
    scatter_kernel<<<(N_EDGES + 255) / 256, 256>>>(srcp, dstp, ew, N_EDGES);

    // layer 0: 128 -> 64  (GEMM then fused CSR aggregation)
    gemm_kernel<128, 64, 64, 64><<<(N_NODES + 63) / 64, 128>>>(x, W0, (float*)p_m, N_NODES);
    node_agg_kernel<16><<<(N_NODES * 16 + 255) / 256, 256>>>((const float*)p_m, b0, (float*)p_h, N_NODES);

    // layer 1: 64 -> 32
    gemm_kernel<64, 32, 128, 32><<<(N_NODES + 127) / 128, 128>>>((const float*)p_h, W1, (float*)p_m2, N_NODES);
    node_agg_kernel<8><<<(N_NODES * 8 + 255) / 256, 256>>>((const float*)p_m2, b1, (float*)p_h2, N_NODES);

    // pooling + MLP
    pool_kernel<<<(N_NODES + 127) / 128, 32>>>((const float*)p_h2, ngi, N_NODES);
    mlp_kernel<<<N_GRAPHS, 128>>>(Wm1, bm1, Wm2, bm2, out);
}

// round 7
// speedup vs baseline: 1.8184x; 1.1538x over previous
#include <cuda_runtime.h>
#include <cuda_bf16.h>

#define N_NODES  100000
#define N_EDGES  1600000
#define N_GRAPHS 1000
#define SCAN_B   1024
#define N_SBLK   ((N_NODES + SCAN_B - 1) / SCAN_B)   // 98

// ---------------- scratch (static __device__, no allocs) ----------------
__device__ float g_deg[N_NODES];
__device__ float g_dinv[N_NODES];
__device__ int   g_cnt[N_NODES];
__device__ int   g_rank[N_EDGES];
__device__ int   g_rs[N_NODES + 1];
__device__ int   g_bsum[N_SBLK];
__device__ int2  g_csr[N_EDGES];          // {src, weight-as-bits}
__device__ float g_m[N_NODES * 64];
__device__ float g_h[N_NODES * 64];
__device__ float g_m2[N_NODES * 32];
__device__ float g_h2[N_NODES * 32];

// ---------------- degree + in-degree count + rank capture ----------------
__global__ void edge_prep_kernel(const int* __restrict__ dst, const float* __restrict__ w, int E) {
    int e = blockIdx.x * blockDim.x + threadIdx.x;
    if (e < E) {
        int d = dst[e];
        atomicAdd(&g_deg[d], w[e]);
        g_rank[e] = atomicAdd(&g_cnt[d], 1);   // coalesced rank store
    }
}

// ---------------- fused dinv + scan stage 1 ----------------
__global__ void dinv_scan1_kernel(int n) {
    __shared__ int wsum[32];
    int i = blockIdx.x * SCAN_B + threadIdx.x;
    int lane = threadIdx.x & 31, wid = threadIdx.x >> 5;

    if (i < n) {
        float d = g_deg[i] + 1.0f;  // self loop weight 1
        g_dinv[i] = rsqrtf(fmaxf(d, 1e-12f));
    }
    if (i == 0) g_rs[0] = 0;

    int v = (i < n) ? g_cnt[i] : 0;
    int s = v;
#pragma unroll
    for (int o = 1; o < 32; o <<= 1) {
        int t = __shfl_up_sync(0xffffffffu, s, o);
        if (lane >= o) s += t;
    }
    if (lane == 31) wsum[wid] = s;
    __syncthreads();
    if (wid == 0) {
        int ws = wsum[lane];
#pragma unroll
        for (int o = 1; o < 32; o <<= 1) {
            int t = __shfl_up_sync(0xffffffffu, ws, o);
            if (lane >= o) ws += t;
        }
        wsum[lane] = ws;
    }
    __syncthreads();
    int off = (wid > 0) ? wsum[wid - 1] : 0;
    int incl = s + off;
    if (i < n) g_rs[i + 1] = incl;
    if (threadIdx.x == SCAN_B - 1) g_bsum[blockIdx.x] = incl;
}

__global__ void scan2_kernel(int nb) {   // nb <= 128, 128 threads
    __shared__ int sm[4];
    int lane = threadIdx.x & 31, wid = threadIdx.x >> 5;
    int v = (threadIdx.x < nb) ? g_bsum[threadIdx.x] : 0;
    int s = v;
#pragma unroll
    for (int o = 1; o < 32; o <<= 1) {
        int t = __shfl_up_sync(0xffffffffu, s, o);
        if (lane >= o) s += t;
    }
    if (lane == 31) sm[wid] = s;
    __syncthreads();
    int off = 0;
    for (int w = 0; w < wid; w++) off += sm[w];
    if (threadIdx.x < nb) g_bsum[threadIdx.x] = s + off;
}

__global__ void scan3_kernel(int n) {
    if (blockIdx.x == 0) return;
    int i = blockIdx.x * SCAN_B + threadIdx.x;
    if (i < n) g_rs[i + 1] += g_bsum[blockIdx.x - 1];
}

// ---------------- scatter into CSR (atomic-free, single packed STG.64) ----------------
__global__ void scatter_kernel(const int* __restrict__ src, const int* __restrict__ dst,
                               const float* __restrict__ w, int E) {
    int e = blockIdx.x * blockDim.x + threadIdx.x;
    if (e >= E) return;
    int s = src[e], d = dst[e];
    int pos = g_rs[d] + g_rank[e];
    float nw = g_dinv[s] * w[e] * g_dinv[d];
    g_csr[pos] = make_int2(s, __float_as_int(nw));
}

// ---------------- register-blocked GEMM: out[N,M] = X[N,K] @ W[K,M] ----------------
// 4 rows x 8 cols per thread; both X and W staged in KP-sized K phases.
template <int K, int M, int TR, int KP>
__global__ void __launch_bounds__(TR * M / 32)
gemm_kernel(const float* __restrict__ X, const float* __restrict__ W,
            float* __restrict__ out, int nrows) {
    __shared__ float Ws[KP * M];
    __shared__ float Xs[TR * KP];
    constexpr int T = TR * M / 32;

    int row0 = blockIdx.x * TR;
    int nr = nrows - row0; if (nr > TR) nr = TR;
    const float4* Xg = reinterpret_cast<const float4*>(X);

    int tx = threadIdx.x % (M / 8);
    int ty = threadIdx.x / (M / 8);
    int c0 = tx * 8;
    int r0 = ty * 4;

    float acc[4][8];
#pragma unroll
    for (int r = 0; r < 4; r++)
#pragma unroll
        for (int c = 0; c < 8; c++) acc[r][c] = 0.f;

    for (int ph = 0; ph < K; ph += KP) {
        for (int i = threadIdx.x; i < KP * M / 4; i += T)
            reinterpret_cast<float4*>(Ws)[i] = reinterpret_cast<const float4*>(W + ph * M)[i];
        for (int i = threadIdx.x; i < nr * (KP / 4); i += T) {
            int row = i / (KP / 4), col = i % (KP / 4);
            reinterpret_cast<float4*>(Xs)[row * (KP / 4) + col] =
                Xg[((size_t)(row0 + row) * K + ph) / 4 + col];
        }
        __syncthreads();

#pragma unroll 2
        for (int kc = 0; kc < KP; kc += 4) {
            float4 xa[4];
#pragma unroll
            for (int r = 0; r < 4; r++)
                xa[r] = *reinterpret_cast<const float4*>(&Xs[(r0 + r) * KP + kc]);
#pragma unroll
            for (int kk = 0; kk < 4; kk++) {
                float4 wa = *reinterpret_cast<const float4*>(&Ws[(kc + kk) * M + c0]);
                float4 wb = *reinterpret_cast<const float4*>(&Ws[(kc + kk) * M + c0 + 4]);
#pragma unroll
                for (int r = 0; r < 4; r++) {
                    float xv = (&xa[r].x)[kk];
                    acc[r][0] += xv * wa.x; acc[r][1] += xv * wa.y;
                    acc[r][2] += xv * wa.z; acc[r][3] += xv * wa.w;
                    acc[r][4] += xv * wb.x; acc[r][5] += xv * wb.y;
                    acc[r][6] += xv * wb.z; acc[r][7] += xv * wb.w;
                }
            }
        }
        __syncthreads();
    }

#pragma unroll
    for (int r = 0; r < 4; r++) {
        int row = row0 + r0 + r;
        if (row < nrows) {
            *reinterpret_cast<float4*>(&out[(size_t)row * M + c0]) =
                make_float4(acc[r][0], acc[r][1], acc[r][2], acc[r][3]);
            *reinterpret_cast<float4*>(&out[(size_t)row * M + c0 + 4]) =
                make_float4(acc[r][4], acc[r][5], acc[r][6], acc[r][7]);
        }
    }
}

// ---------------- CSR node aggregation, fused self-loop + bias + relu ----------------
// FD4 threads per node (float4 features each): 16 for F=64, 8 for F=32.
template <int FD4>
__global__ void node_agg_kernel(const float* __restrict__ m, const float* __restrict__ b,
                                float* __restrict__ h, int n) {
    int gid = (blockIdx.x * blockDim.x + threadIdx.x) / FD4;
    int f = threadIdx.x % FD4;
    if (gid >= n) return;
    const float4* m4 = reinterpret_cast<const float4*>(m);

    float di = g_dinv[gid];
    float ws = di * di;                        // self-loop weight
    float4 acc = m4[(size_t)gid * FD4 + f];
    acc.x *= ws; acc.y *= ws; acc.z *= ws; acc.w *= ws;

    int p = g_rs[gid], p1 = g_rs[gid + 1];
    for (; p + 1 < p1; p += 2) {
        int2  c0 = g_csr[p], c1 = g_csr[p + 1];
        float w0 = __int_as_float(c0.y), w1 = __int_as_float(c1.y);
        float4 v0 = m4[(size_t)c0.x * FD4 + f];
        float4 v1 = m4[(size_t)c1.x * FD4 + f];
        acc.x += v0.x * w0 + v1.x * w1;
        acc.y += v0.y * w0 + v1.y * w1;
        acc.z += v0.z * w0 + v1.z * w1;
        acc.w += v0.w * w0 + v1.w * w1;
    }
    if (p < p1) {
        int2 c0 = g_csr[p];
        float w0 = __int_as_float(c0.y);
        float4 v0 = m4[(size_t)c0.x * FD4 + f];
        acc.x += v0.x * w0; acc.y += v0.y * w0;
        acc.z += v0.z * w0; acc.w += v0.w * w0;
    }

    float4 bb = reinterpret_cast<const float4*>(b)[f];
    acc.x = fmaxf(acc.x + bb.x, 0.f);
    acc.y = fmaxf(acc.y + bb.y, 0.f);
    acc.z = fmaxf(acc.z + bb.z, 0.f);
    acc.w = fmaxf(acc.w + bb.w, 0.f);
    reinterpret_cast<float4*>(h)[(size_t)gid * FD4 + f] = acc;
}

// ---------------- fused pool + MLP: block b sums graph b's rows then does the MLP ----------------
__global__ void poolmlp_kernel(const float* __restrict__ h2, const int* __restrict__ ngi,
                               const float* __restrict__ Wm1, const float* __restrict__ bm1,
                               const float* __restrict__ Wm2, const float* __restrict__ bm2,
                               float* __restrict__ out) {
    __shared__ int bounds[2];
    __shared__ float red[4][32];
    __shared__ float gs[32];
    __shared__ float g2s[128];

    int b = blockIdx.x, t = threadIdx.x;

    if (t < 2) {
        int target = b + t;            // lower_bound(ngi, target)
        int lo = 0, hi = N_NODES;
        while (lo < hi) {
            int mid = (lo + hi) >> 1;
            if (ngi[mid] < target) lo = mid + 1; else hi = mid;
        }
        bounds[t] = lo;
    }
    __syncthreads();
    int start = bounds[0], end = bounds[1];

    int lane = t & 31, r = t >> 5;     // 4 row-strides x 32 feature lanes
    float acc = 0.f;
    for (int i = start + r; i < end; i += 4)
        acc += h2[(size_t)i * 32 + lane];
    red[r][lane] = acc;
    __syncthreads();
    if (t < 32) gs[t] = red[0][t] + red[1][t] + red[2][t] + red[3][t];
    __syncthreads();

    float a1 = bm1[t];
#pragma unroll
    for (int k = 0; k < 32; k++) a1 += gs[k] * Wm1[k * 128 + t];
    g2s[t] = fmaxf(a1, 0.f);
    __syncthreads();
    if (t < 2) {
        float a = bm2[t];
#pragma unroll
        for (int k = 0; k < 128; k++) a += g2s[k] * Wm2[k * 2 + t];
        out[b * 2 + t] = a;
    }
}

// ---------------- host ----------------
extern "C" void kernel_launch(void* const* d_in, const int* in_sizes, int n_in,
                              void* d_out, int out_size) {
    const float* x   = (const float*)d_in[0];
    const int*   ei  = (const int*)d_in[1];
    const float* ew  = (const float*)d_in[2];
    const int*   ngi = (const int*)d_in[3];
    const float* W0  = (const float*)d_in[4];
    const float* b0  = (const float*)d_in[5];
    const float* W1  = (const float*)d_in[6];
    const float* b1  = (const float*)d_in[7];
    const float* Wm1 = (const float*)d_in[8];
    const float* bm1 = (const float*)d_in[9];
    const float* Wm2 = (const float*)d_in[10];
    const float* bm2 = (const float*)d_in[11];
    float* out = (float*)d_out;

    const int* srcp = ei;
    const int* dstp = ei + N_EDGES;

    // one-time side stream + fork/join events (created on the uncaptured
    // correctness call; capture sees a fixed, deterministic graph every time)
    static cudaStream_t s2 = nullptr;
    static cudaEvent_t  e_fork = nullptr, e_join = nullptr;
    if (s2 == nullptr) {
        cudaStreamCreateWithFlags(&s2, cudaStreamNonBlocking);
        cudaEventCreateWithFlags(&e_fork, cudaEventDisableTiming);
        cudaEventCreateWithFlags(&e_join, cudaEventDisableTiming);
    }

    void *p_deg, *p_cnt, *p_m, *p_h, *p_m2, *p_h2;
    cudaGetSymbolAddress(&p_deg, g_deg);
    cudaGetSymbolAddress(&p_cnt, g_cnt);
    cudaGetSymbolAddress(&p_m,   g_m);
    cudaGetSymbolAddress(&p_h,   g_h);
    cudaGetSymbolAddress(&p_m2,  g_m2);
    cudaGetSymbolAddress(&p_h2,  g_h2);

    // ---- fork: CSR/normalization build on s2, gemm0 on the main stream ----
    cudaEventRecord(e_fork, 0);
    cudaStreamWaitEvent(s2, e_fork, 0);

    cudaMemsetAsync(p_deg, 0, N_NODES * sizeof(float), s2);
    cudaMemsetAsync(p_cnt, 0, N_NODES * sizeof(int), s2);
    edge_prep_kernel<<<(N_EDGES + 255) / 256, 256, 0, s2>>>(dstp, ew, N_EDGES);
    dinv_scan1_kernel<<<N_SBLK, SCAN_B, 0, s2>>>(N_NODES);
    scan2_kernel<<<1, 128, 0, s2>>>(N_SBLK);
    scan3_kernel<<<N_SBLK, SCAN_B, 0, s2>>>(N_NODES);
    scatter_kernel<<<(N_EDGES + 255) / 256, 256, 0, s2>>>(srcp, dstp, ew, N_EDGES);
    cudaEventRecord(e_join, s2);

    // main stream: layer-0 GEMM runs concurrently with the build
    gemm_kernel<128, 64, 64, 64><<<(N_NODES + 63) / 64, 128>>>(x, W0, (float*)p_m, N_NODES);

    // ---- join, then the rest is serial on the main stream ----
    cudaStreamWaitEvent(0, e_join, 0);

    node_agg_kernel<16><<<(N_NODES * 16 + 255) / 256, 256>>>((const float*)p_m, b0, (float*)p_h, N_NODES);

    gemm_kernel<64, 32, 128, 32><<<(N_NODES + 127) / 128, 128>>>((const float*)p_h, W1, (float*)p_m2, N_NODES);
    node_agg_kernel<8><<<(N_NODES * 8 + 255) / 256, 256>>>((const float*)p_m2, b1, (float*)p_h2, N_NODES);

    poolmlp_kernel<<<N_GRAPHS, 128>>>((const float*)p_h2, ngi, Wm1, bm1, Wm2, bm2, out);
}